// round 16
// baseline (speedup 1.0000x reference)
#include <cuda_runtime.h>
#include <cuda_bf16.h>
#include <math.h>

#define Nd    128
#define SLICE (Nd * Nd)          // 16384
#define VOL   (Nd * Nd * Nd)     // 2097152
#define NVOLS 8                  // 2 batches * 4 classes
#define P3_BLOCKS 512            // pass3 grid size (8 * 32 * 2)

// Per-block partials: every slot is overwritten on every run -> NO init kernel,
// NO atomics, fully deterministic, graph-safe.
__device__ double g_pS1[NVOLS][Nd];
__device__ double g_pS2[NVOLS][Nd];
__device__ double g_pNum[P3_BLOCKS];
__device__ double g_pDen[P3_BLOCKS];
__device__ __nv_bfloat16 g_scrB[(size_t)NVOLS * VOL];  // 32 MiB: WH-blurred labels

// Gaussian taps exp(-x^2/(2*25)), x=-4..4 (unnormalized, matches reference)
__constant__ float Gc[9] = {
    0.72614903f, 0.83527021f, 0.92311635f, 0.98019867f, 1.0f,
    0.98019867f, 0.92311635f, 0.83527021f, 0.72614903f
};

// Block-wide reduce of two floats; thread 0 gets the (double) totals.
__device__ __forceinline__ bool blockReducePair(float a, float b, double* outA, double* outB) {
    const int tid  = threadIdx.x + threadIdx.y * blockDim.x;
    const int lane = tid & 31;
    const int wid  = tid >> 5;
    #pragma unroll
    for (int off = 16; off; off >>= 1) {
        a += __shfl_down_sync(0xffffffffu, a, off);
        b += __shfl_down_sync(0xffffffffu, b, off);
    }
    __shared__ float sa[16], sb_[16];
    if (lane == 0) { sa[wid] = a; sb_[wid] = b; }
    __syncthreads();   // also orders phase-A smem stores before phase-B in k_pass12
    if (tid == 0) {
        const int nw = (blockDim.x * blockDim.y) >> 5;
        double A = 0.0, B = 0.0;
        for (int i = 0; i < nw; ++i) { A += (double)sa[i]; B += (double)sb_[i]; }
        *outA = A; *outB = B;
        return true;
    }
    return false;
}

// ---------------------------------------------------------------------------
// Fused pass 1+2 (per (iv,d) slice, 512 threads, 64KB dynamic smem):
//  Phase A: warp owns 8 rows; float4 loads, S1/S2 sums, W-blur via +/-1-lane
//    float4 shuffles, W-blurred rows to smem (STS.128, conflict-free).
//  Phase B: thread -> (column, 32-row group); H-blur from smem columns with a
//    straight-line carry8+load8 buffer; bf16 direct to g_scrB.
//  Block partial sums land in g_pS1/g_pS2[iv][d] (non-atomic).
// ---------------------------------------------------------------------------
__global__ void __launch_bounds__(512) k_pass12(const float* __restrict__ labels,
                                                const float* __restrict__ inputs) {
    extern __shared__ float sb[];                 // [128][128] = 64 KB
    const int iv   = blockIdx.x;
    const int d    = blockIdx.y;
    const int t    = threadIdx.x;
    const int lane = t & 31;
    const int wp   = t >> 5;                      // warp 0..15
    const size_t vbase = (size_t)iv * VOL + (size_t)d * SLICE;
    const float4* __restrict__ L4 = (const float4*)(labels + vbase);
    const float4* __restrict__ I4 = (const float4*)(inputs + (size_t)(iv >> 2) * VOL
                                                           + (size_t)d * SLICE);

    // ---- Phase A: W-blur 8 rows per warp ----
    float sumP = 0.f, sumPI = 0.f;
    #pragma unroll
    for (int r = 0; r < 8; ++r) {
        const int h   = wp * 8 + r;
        const int idx = h * 32 + lane;
        const float4 p  = L4[idx];
        const float4 vi = I4[idx];
        sumP  += (p.x + p.y) + (p.z + p.w);
        sumPI += (p.x * vi.x + p.y * vi.y) + (p.z * vi.z + p.w * vi.w);

        float a[12];
        a[0] = __shfl_up_sync(0xffffffffu, p.x, 1);
        a[1] = __shfl_up_sync(0xffffffffu, p.y, 1);
        a[2] = __shfl_up_sync(0xffffffffu, p.z, 1);
        a[3] = __shfl_up_sync(0xffffffffu, p.w, 1);
        a[4] = p.x; a[5] = p.y; a[6] = p.z; a[7] = p.w;
        a[8]  = __shfl_down_sync(0xffffffffu, p.x, 1);
        a[9]  = __shfl_down_sync(0xffffffffu, p.y, 1);
        a[10] = __shfl_down_sync(0xffffffffu, p.z, 1);
        a[11] = __shfl_down_sync(0xffffffffu, p.w, 1);
        if (lane == 0)  { a[0] = a[1] = a[2]  = a[3]  = 0.f; }
        if (lane == 31) { a[8] = a[9] = a[10] = a[11] = 0.f; }

        float o0 = 0.f, o1 = 0.f, o2 = 0.f, o3 = 0.f;
        #pragma unroll
        for (int j = 0; j < 9; ++j) {
            o0 += Gc[j] * a[j];
            o1 += Gc[j] * a[j + 1];
            o2 += Gc[j] * a[j + 2];
            o3 += Gc[j] * a[j + 3];
        }
        ((float4*)(sb + h * Nd))[lane] = make_float4(o0, o1, o2, o3);
    }

    // barrier inside; thread 0 writes this block's partial (no atomic, no init)
    {
        double A, B;
        if (blockReducePair(sumPI, sumP, &A, &B)) {
            g_pS1[iv][d] = A;
            g_pS2[iv][d] = B;
        }
    }

    // ---- Phase B: H-blur, 32 rows per thread, straight-line buffer ----
    const int w2 = t & 127;                       // column
    const int hg = t >> 7;                        // row group 0..3
    __nv_bfloat16* __restrict__ dst = g_scrB + vbase;

    float carry[8];
    #pragma unroll
    for (int k = 0; k < 8; ++k) {
        const int hh = hg * 32 - 4 + k;
        carry[k] = (hh >= 0) ? sb[hh * Nd + w2] : 0.f;
    }
    #pragma unroll
    for (int g = 0; g < 4; ++g) {
        const int hb = hg * 32 + g * 8;
        float nx[8];
        #pragma unroll
        for (int k = 0; k < 8; ++k) {
            const int hh = hb + 4 + k;
            nx[k] = (hh < Nd) ? sb[hh * Nd + w2] : 0.f;
        }
        float buf[16];
        #pragma unroll
        for (int k = 0; k < 8; ++k) { buf[k] = carry[k]; buf[8 + k] = nx[k]; }
        #pragma unroll
        for (int k = 0; k < 8; ++k) {
            float acc = 0.f;
            #pragma unroll
            for (int j = 0; j < 9; ++j) acc += Gc[j] * buf[k + j];
            dst[(hb + k) * Nd + w2] = __float2bfloat16(acc);
        }
        #pragma unroll
        for (int k = 0; k < 8; ++k) carry[k] = nx[k];
    }
}

// ---------------------------------------------------------------------------
// Pass 3 (2-wide): each thread owns a w-pair. bf16x2 scr loads + float2
// label/input loads -> half the load instructions per byte vs scalar.
// Warp 0 first reduces the 128 S-partials (L2) to get the class mean.
// D-blur straight-line buffer (carry8 + load4 per group), fused with
//   w = exp(-((in-mean)^2)^2),  num += blur(p)*p*w,  den += blur(p)*w.
// Block partial Num/Den -> g_pNum/g_pDen[bid] (non-atomic).
// ---------------------------------------------------------------------------
__global__ void __launch_bounds__(256) k_pass3(const float* __restrict__ labels,
                                               const float* __restrict__ inputs) {
    const int iv = blockIdx.x;                                  // 0..7
    const int h  = blockIdx.y * blockDim.y + threadIdx.y;       // 0..127
    const int d0 = blockIdx.z * 64;                             // 0 or 64
    const int wp = threadIdx.x;                                 // w-pair 0..63
    const int tid = threadIdx.y * 64 + threadIdx.x;

    __shared__ float s_mean;
    if (tid < 32) {                       // warp 0: reduce S partials -> mean
        double s1 = 0.0, s2 = 0.0;
        #pragma unroll
        for (int j = tid; j < Nd; j += 32) { s1 += g_pS1[iv][j]; s2 += g_pS2[iv][j]; }
        #pragma unroll
        for (int off = 16; off; off >>= 1) {
            s1 += __shfl_down_sync(0xffffffffu, s1, off);
            s2 += __shfl_down_sync(0xffffffffu, s2, off);
        }
        if (tid == 0) s_mean = (float)(s1 / (s2 + 1e-5 * (double)VOL));
    }
    __syncthreads();
    const float mean = s_mean;

    const __nv_bfloat162* __restrict__ S2p = (const __nv_bfloat162*)(g_scrB + (size_t)iv * VOL);
    const float2* __restrict__ L2p = (const float2*)(labels + (size_t)iv * VOL);
    const float2* __restrict__ I2p = (const float2*)(inputs + (size_t)(iv >> 2) * VOL);
    const int hw2 = h * (Nd / 2) + wp;            // pair index within slice

    float2 carry[8];
    #pragma unroll
    for (int k = 0; k < 8; ++k) {
        const int dd = d0 - 4 + k;
        if (dd >= 0) {
            const __nv_bfloat162 v = S2p[dd * (SLICE / 2) + hw2];
            carry[k] = make_float2(__bfloat162float(v.x), __bfloat162float(v.y));
        } else carry[k] = make_float2(0.f, 0.f);
    }
    float numA = 0.f, denA = 0.f;
    for (int d = d0; d < d0 + 64; d += 4) {
        float2 nS[4], nP[4], nV[4];
        #pragma unroll
        for (int k = 0; k < 4; ++k) {             // 12 independent wide loads
            const int dd = d + k;
            if (dd + 4 < Nd) {
                const __nv_bfloat162 v = S2p[(dd + 4) * (SLICE / 2) + hw2];
                nS[k] = make_float2(__bfloat162float(v.x), __bfloat162float(v.y));
            } else nS[k] = make_float2(0.f, 0.f);
            nP[k] = L2p[dd * (SLICE / 2) + hw2];
            nV[k] = I2p[dd * (SLICE / 2) + hw2];
        }
        float2 buf[12];
        #pragma unroll
        for (int k = 0; k < 8; ++k) buf[k] = carry[k];
        #pragma unroll
        for (int k = 0; k < 4; ++k) buf[8 + k] = nS[k];
        #pragma unroll
        for (int k = 0; k < 4; ++k) {
            float bx = 0.f, by = 0.f;
            #pragma unroll
            for (int j = 0; j < 9; ++j) {
                bx += Gc[j] * buf[k + j].x;
                by += Gc[j] * buf[k + j].y;
            }
            float dfx = nV[k].x - mean; dfx *= dfx;
            float dfy = nV[k].y - mean; dfy *= dfy;
            const float wx = __expf(-dfx * dfx);
            const float wy = __expf(-dfy * dfy);
            numA += bx * nP[k].x * wx + by * nP[k].y * wy;
            denA += bx * wx + by * wy;
        }
        #pragma unroll
        for (int k = 0; k < 8; ++k) carry[k] = buf[4 + k];
    }
    {
        double A, B;
        if (blockReducePair(numA, denA, &A, &B)) {
            const int bid = blockIdx.x + 8 * (blockIdx.y + 32 * blockIdx.z);
            g_pNum[bid] = A;
            g_pDen[bid] = B;
        }
    }
}

// ---------------------------------------------------------------------------
// Final: reduce 512 Num/Den partials per class, combine batches, write loss.
// Warp i handles iv=i (partials at bid = i + 8*j).
// ---------------------------------------------------------------------------
__global__ void k_final(float* __restrict__ out) {
    const int tid  = threadIdx.x;          // 0..255
    const int lane = tid & 31;
    const int wrp  = tid >> 5;             // 0..7 = iv
    __shared__ double sN[NVOLS], sD[NVOLS];
    double n = 0.0, dsum = 0.0;
    #pragma unroll
    for (int j = lane; j < 64; j += 32) {  // 64 (y,z) blocks per iv
        const int bid = wrp + 8 * j;
        n    += g_pNum[bid];
        dsum += g_pDen[bid];
    }
    #pragma unroll
    for (int off = 16; off; off >>= 1) {
        n    += __shfl_down_sync(0xffffffffu, n, off);
        dsum += __shfl_down_sync(0xffffffffu, dsum, off);
    }
    if (lane == 0) { sN[wrp] = n; sD[wrp] = dsum; }
    __syncthreads();
    if (tid == 0) {
        double loss = 0.0;
        for (int k = 0; k < 4; ++k) {
            const double nn = sN[k] + sN[k + 4];
            const double dd = sD[k] + sD[k + 4];
            loss += fabs(nn / (dd + 1e-6));
        }
        out[0] = (float)(4.0 - loss);
    }
}

extern "C" void kernel_launch(void* const* d_in, const int* in_sizes, int n_in,
                              void* d_out, int out_size) {
    const float* labels = (const float*)d_in[0];
    const float* inputs = (const float*)d_in[1];
    if (n_in >= 2 && in_sizes[0] < in_sizes[1]) {
        labels = (const float*)d_in[1];
        inputs = (const float*)d_in[0];
    }
    cudaFuncSetAttribute(k_pass12, cudaFuncAttributeMaxDynamicSharedMemorySize, 65536);
    k_pass12<<<dim3(NVOLS, Nd), 512, 65536>>>(labels, inputs);
    k_pass3<<<dim3(NVOLS, 32, 2), dim3(64, 4)>>>(labels, inputs);
    k_final<<<1, 256>>>((float*)d_out);
    (void)out_size;
}

// round 17
// speedup vs baseline: 1.1018x; 1.1018x over previous
#include <cuda_runtime.h>
#include <cuda_bf16.h>
#include <math.h>

#define Nd    128
#define SLICE (Nd * Nd)          // 16384
#define VOL   (Nd * Nd * Nd)     // 2097152
#define NVOLS 8                  // 2 batches * 4 classes
#define P3_BLOCKS (8 * 64 * 2)   // pass3 grid size = 1024

// Per-block partials: every slot overwritten every run -> NO init kernel,
// NO atomics, deterministic, graph-safe.
__device__ double g_pS1[NVOLS][Nd];
__device__ double g_pS2[NVOLS][Nd];
__device__ double g_pNum[P3_BLOCKS];
__device__ double g_pDen[P3_BLOCKS];
__device__ __nv_bfloat16 g_scrB[(size_t)NVOLS * VOL];  // 32 MiB: WH-blurred labels

// Gaussian taps exp(-x^2/(2*25)), x=-4..4 (unnormalized, matches reference)
__constant__ float Gc[9] = {
    0.72614903f, 0.83527021f, 0.92311635f, 0.98019867f, 1.0f,
    0.98019867f, 0.92311635f, 0.83527021f, 0.72614903f
};

struct alignas(8) bf16x4 { __nv_bfloat162 a, b; };

// Block-wide reduce of two floats; returns true on thread 0 with totals.
__device__ __forceinline__ bool blockReducePair(float a, float b, double* outA, double* outB) {
    const int tid  = threadIdx.x + threadIdx.y * blockDim.x;
    const int lane = tid & 31;
    const int wid  = tid >> 5;
    #pragma unroll
    for (int off = 16; off; off >>= 1) {
        a += __shfl_down_sync(0xffffffffu, a, off);
        b += __shfl_down_sync(0xffffffffu, b, off);
    }
    __shared__ float sa[16], sb_[16];
    if (lane == 0) { sa[wid] = a; sb_[wid] = b; }
    __syncthreads();   // also orders phase-A smem stores before phase-B in k_pass12
    if (tid == 0) {
        const int nw = (blockDim.x * blockDim.y) >> 5;
        double A = 0.0, B = 0.0;
        for (int i = 0; i < nw; ++i) { A += (double)sa[i]; B += (double)sb_[i]; }
        *outA = A; *outB = B;
        return true;
    }
    return false;
}

// ---------------------------------------------------------------------------
// Fused pass 1+2 (per (iv,d) slice, 512 threads, 32KB dynamic smem = bf16 tile):
//  Phase A: warp owns 8 rows; float4 loads, S1/S2 sums, W-blur via +/-1-lane
//    float4 shuffles, W-blurred row stored to smem as packed bf16x4 (STS.64).
//    bf16 smem halves the tile (64->32KB) -> 3 blocks/SM instead of 2
//    (occ 52% -> ~75%) to cover latency; this kernel was issue/occ-bound.
//  Phase B: thread -> (column, 32-row group); H-blur from smem columns with a
//    straight-line carry8+load8 buffer; bf16 direct to g_scrB.
//  Block partial sums land in g_pS1/g_pS2[iv][d] (non-atomic).
// ---------------------------------------------------------------------------
__global__ void __launch_bounds__(512) k_pass12(const float* __restrict__ labels,
                                                const float* __restrict__ inputs) {
    extern __shared__ __nv_bfloat16 sb16[];       // [128][128] bf16 = 32 KB
    const int iv   = blockIdx.x;
    const int d    = blockIdx.y;
    const int t    = threadIdx.x;
    const int lane = t & 31;
    const int wp   = t >> 5;                      // warp 0..15
    const size_t vbase = (size_t)iv * VOL + (size_t)d * SLICE;
    const float4* __restrict__ L4 = (const float4*)(labels + vbase);
    const float4* __restrict__ I4 = (const float4*)(inputs + (size_t)(iv >> 2) * VOL
                                                           + (size_t)d * SLICE);

    // ---- Phase A: W-blur 8 rows per warp ----
    float sumP = 0.f, sumPI = 0.f;
    #pragma unroll
    for (int r = 0; r < 8; ++r) {
        const int h   = wp * 8 + r;
        const int idx = h * 32 + lane;
        const float4 p  = L4[idx];
        const float4 vi = I4[idx];
        sumP  += (p.x + p.y) + (p.z + p.w);
        sumPI += (p.x * vi.x + p.y * vi.y) + (p.z * vi.z + p.w * vi.w);

        float a[12];
        a[0] = __shfl_up_sync(0xffffffffu, p.x, 1);
        a[1] = __shfl_up_sync(0xffffffffu, p.y, 1);
        a[2] = __shfl_up_sync(0xffffffffu, p.z, 1);
        a[3] = __shfl_up_sync(0xffffffffu, p.w, 1);
        a[4] = p.x; a[5] = p.y; a[6] = p.z; a[7] = p.w;
        a[8]  = __shfl_down_sync(0xffffffffu, p.x, 1);
        a[9]  = __shfl_down_sync(0xffffffffu, p.y, 1);
        a[10] = __shfl_down_sync(0xffffffffu, p.z, 1);
        a[11] = __shfl_down_sync(0xffffffffu, p.w, 1);
        if (lane == 0)  { a[0] = a[1] = a[2]  = a[3]  = 0.f; }
        if (lane == 31) { a[8] = a[9] = a[10] = a[11] = 0.f; }

        float o0 = 0.f, o1 = 0.f, o2 = 0.f, o3 = 0.f;
        #pragma unroll
        for (int j = 0; j < 9; ++j) {
            o0 += Gc[j] * a[j];
            o1 += Gc[j] * a[j + 1];
            o2 += Gc[j] * a[j + 2];
            o3 += Gc[j] * a[j + 3];
        }
        bf16x4 pk;
        pk.a = __floats2bfloat162_rn(o0, o1);
        pk.b = __floats2bfloat162_rn(o2, o3);
        ((bf16x4*)(sb16 + h * Nd))[lane] = pk;    // STS.64, conflict-free
    }

    // barrier inside; thread 0 writes this block's partial (no atomic, no init)
    {
        double A, B;
        if (blockReducePair(sumPI, sumP, &A, &B)) {
            g_pS1[iv][d] = A;
            g_pS2[iv][d] = B;
        }
    }

    // ---- Phase B: H-blur, 32 rows per thread, straight-line buffer ----
    const int w2 = t & 127;                       // column
    const int hg = t >> 7;                        // row group 0..3
    __nv_bfloat16* __restrict__ dst = g_scrB + vbase;

    float carry[8];
    #pragma unroll
    for (int k = 0; k < 8; ++k) {
        const int hh = hg * 32 - 4 + k;
        carry[k] = (hh >= 0) ? __bfloat162float(sb16[hh * Nd + w2]) : 0.f;
    }
    #pragma unroll
    for (int g = 0; g < 4; ++g) {
        const int hb = hg * 32 + g * 8;
        float nx[8];
        #pragma unroll
        for (int k = 0; k < 8; ++k) {             // 8 independent LDS, batched
            const int hh = hb + 4 + k;
            nx[k] = (hh < Nd) ? __bfloat162float(sb16[hh * Nd + w2]) : 0.f;
        }
        float buf[16];
        #pragma unroll
        for (int k = 0; k < 8; ++k) { buf[k] = carry[k]; buf[8 + k] = nx[k]; }
        #pragma unroll
        for (int k = 0; k < 8; ++k) {
            float acc = 0.f;
            #pragma unroll
            for (int j = 0; j < 9; ++j) acc += Gc[j] * buf[k + j];
            dst[(hb + k) * Nd + w2] = __float2bfloat16(acc);
        }
        #pragma unroll
        for (int k = 0; k < 8; ++k) carry[k] = nx[k];
    }
}

// ---------------------------------------------------------------------------
// Pass 3 (scalar — the round-15 form that measured fastest): D-blur over bf16
// g_scrB fused with weights + num/den reductions (blur self-adjointness).
// Straight-line carry8+load8 buffer, 24 independent loads per 8-output group.
//   num = sum(blur3(p)*p*w), den = sum(blur3(p)*w), w = exp(-((in-mean)^2)^2)
// Warp 0 first reduces the 128 S-partials to get the class mean.
// Block partial Num/Den -> g_pNum/g_pDen[bid] (non-atomic).
// ---------------------------------------------------------------------------
__global__ void __launch_bounds__(256) k_pass3(const float* __restrict__ labels,
                                               const float* __restrict__ inputs) {
    const int iv = blockIdx.x;                                  // 0..7
    const int h  = blockIdx.y * blockDim.y + threadIdx.y;       // 0..127
    const int d0 = blockIdx.z * 64;                             // 0 or 64
    const int w  = threadIdx.x;                                 // 0..127
    const int tid = threadIdx.y * 128 + threadIdx.x;

    __shared__ float s_mean;
    if (tid < 32) {                       // warp 0: reduce S partials -> mean
        double s1 = 0.0, s2 = 0.0;
        #pragma unroll
        for (int j = tid; j < Nd; j += 32) { s1 += g_pS1[iv][j]; s2 += g_pS2[iv][j]; }
        #pragma unroll
        for (int off = 16; off; off >>= 1) {
            s1 += __shfl_down_sync(0xffffffffu, s1, off);
            s2 += __shfl_down_sync(0xffffffffu, s2, off);
        }
        if (tid == 0) s_mean = (float)(s1 / (s2 + 1e-5 * (double)VOL));
    }
    __syncthreads();
    const float mean = s_mean;

    const __nv_bfloat16* __restrict__ S = g_scrB + (size_t)iv * VOL;
    const float* __restrict__ Lv = labels + (size_t)iv * VOL;
    const float* __restrict__ Iv = inputs + (size_t)(iv >> 2) * VOL;
    const int hw = h * Nd + w;

    float carry[8];
    #pragma unroll
    for (int k = 0; k < 8; ++k) {
        const int dd = d0 - 4 + k;
        carry[k] = (dd >= 0) ? __bfloat162float(S[(size_t)dd * SLICE + hw]) : 0.f;
    }
    float numA = 0.f, denA = 0.f;
    for (int d = d0; d < d0 + 64; d += 8) {
        float nS[8], nP[8], nV[8];
        #pragma unroll
        for (int k = 0; k < 8; ++k) {             // 24 independent loads, batched
            const int dd = d + k;
            nS[k] = (dd + 4 < Nd) ? __bfloat162float(S[(size_t)(dd + 4) * SLICE + hw]) : 0.f;
            nP[k] = Lv[(size_t)dd * SLICE + hw];
            nV[k] = Iv[(size_t)dd * SLICE + hw];
        }
        float buf[16];
        #pragma unroll
        for (int k = 0; k < 8; ++k) { buf[k] = carry[k]; buf[8 + k] = nS[k]; }
        #pragma unroll
        for (int k = 0; k < 8; ++k) {
            float bp = 0.f;
            #pragma unroll
            for (int j = 0; j < 9; ++j) bp += Gc[j] * buf[k + j];
            float df = nV[k] - mean;
            df *= df;
            const float wgt = __expf(-df * df);
            numA += bp * nP[k] * wgt;
            denA += bp * wgt;
        }
        #pragma unroll
        for (int k = 0; k < 8; ++k) carry[k] = nS[k];
    }
    {
        double A, B;
        if (blockReducePair(numA, denA, &A, &B)) {
            const int bid = blockIdx.x + 8 * (blockIdx.y + 64 * blockIdx.z);
            g_pNum[bid] = A;
            g_pDen[bid] = B;
        }
    }
}

// ---------------------------------------------------------------------------
// Final: reduce 1024 Num/Den partials (128 per class), combine batches.
// Warp i handles iv=i (partials at bid = i + 8*j, j in [0,128)).
// ---------------------------------------------------------------------------
__global__ void k_final(float* __restrict__ out) {
    const int tid  = threadIdx.x;          // 0..255
    const int lane = tid & 31;
    const int wrp  = tid >> 5;             // 0..7 = iv
    __shared__ double sN[NVOLS], sD[NVOLS];
    double n = 0.0, dsum = 0.0;
    #pragma unroll
    for (int j = lane; j < 128; j += 32) { // 128 (y,z) blocks per iv
        const int bid = wrp + 8 * j;
        n    += g_pNum[bid];
        dsum += g_pDen[bid];
    }
    #pragma unroll
    for (int off = 16; off; off >>= 1) {
        n    += __shfl_down_sync(0xffffffffu, n, off);
        dsum += __shfl_down_sync(0xffffffffu, dsum, off);
    }
    if (lane == 0) { sN[wrp] = n; sD[wrp] = dsum; }
    __syncthreads();
    if (tid == 0) {
        double loss = 0.0;
        for (int k = 0; k < 4; ++k) {
            const double nn = sN[k] + sN[k + 4];
            const double dd = sD[k] + sD[k + 4];
            loss += fabs(nn / (dd + 1e-6));
        }
        out[0] = (float)(4.0 - loss);
    }
}

extern "C" void kernel_launch(void* const* d_in, const int* in_sizes, int n_in,
                              void* d_out, int out_size) {
    const float* labels = (const float*)d_in[0];
    const float* inputs = (const float*)d_in[1];
    if (n_in >= 2 && in_sizes[0] < in_sizes[1]) {
        labels = (const float*)d_in[1];
        inputs = (const float*)d_in[0];
    }
    cudaFuncSetAttribute(k_pass12, cudaFuncAttributeMaxDynamicSharedMemorySize, 32768);
    k_pass12<<<dim3(NVOLS, Nd), 512, 32768>>>(labels, inputs);
    k_pass3<<<dim3(NVOLS, 64, 2), dim3(128, 2)>>>(labels, inputs);
    k_final<<<1, 256>>>((float*)d_out);
    (void)out_size;
}